// round 6
// baseline (speedup 1.0000x reference)
#include <cuda_runtime.h>
#include <math.h>
#include <stddef.h>

// ---------------------------------------------------------------------------
// AttnDecoderRNN2 single step, algebraically reduced (validated):
//  * attention window always t in [0,9]; softmax max cancels in L1 norm
//  * zero LSTM state -> Whh unused, f-gate dead (i,g,o rows only: J=3072)
// Round 6: 2 blocks/SM (296 blocks, launch_bounds(256,2)) to double warps/SM;
// two-level grid barrier (16 padded sub-counters) ~0.6us vs ~2.3us;
// rebalanced split-K for 296 slots; dedicated prenet2-finish mini-stage.
// ---------------------------------------------------------------------------

#define GRID    296
#define N_B     64
#define T_ENC   2000
#define ENC     512
#define ATT     256
#define H4      1024
#define G3      3072
#define IN_LSTM 832
#define DECCAT  1536
#define NWIN    10
#define OUT_J   160

#define S_ATT 11
#define S_SP2 4
#define S_P2  16
#define S_L   11
#define S_OUT 32
#define NSUB  16

typedef unsigned long long u64;

// scratch (device globals; allocation forbidden)
__device__ __align__(16) float g_att_parts[S_ATT * 640 * ATT];
__device__ __align__(16) float g_p1_parts [2 * N_B * 512];
__device__ __align__(16) float g_sp2_parts[S_SP2 * N_B * 512];
__device__ __align__(16) float g_p2_parts [S_P2 * N_B * 256];
__device__ __align__(16) float g_sb       [N_B * ATT];
__device__ __align__(16) float g_lstm_parts[S_L * N_B * G3];
__device__ __align__(16) float g_out_parts[S_OUT * N_B * OUT_J];
__device__ __align__(16) float g_inlstm   [N_B * IN_LSTM];
__device__ __align__(16) float g_h1       [N_B * H4];
__device__ __align__(16) float g_dec      [N_B * DECCAT];    // [h2 | context]

// two-level grid barrier state (sub-counters padded to 128B)
__device__ unsigned g_cnt_sub[NSUB * 32];
__device__ unsigned g_cnt_top = 0;
__device__ volatile unsigned g_sense = 0;

struct Ptrs {
    const float *input_enc, *input_dec, *spkr, *speed;
    const float *W_enc, *b_enc, *W_spkr, *conv_prev, *W_speed_att, *W_proj, *b_proj;
    const float *W_sp1, *b_sp1, *W_sp2, *b_sp2;
    const float *W_p1, *b_p1, *W_p2, *b_p2;
    const float *Wih0, *bih0, *bhh0, *Wih1, *bih1, *bhh1, *W_out, *b_out;
    const int *lengths;
    float *out, *ctx_out;
    int write_ctx;
};

__device__ __forceinline__ float sigm(float x) { return 1.f / (1.f + expf(-x)); }

#define FMA2(d, a, b) asm("fma.rn.f32x2 %0,%1,%2,%0;" : "+l"(d) : "l"(a), "l"(b))
#define DUP2(d, s)    asm("mov.b64 %0,{%1,%1};" : "=l"(d) : "f"(s))
#define UNPK(lo, hi, v) asm("mov.b64 {%0,%1},%2;" : "=f"(lo), "=f"(hi) : "l"(v))

enum { M_ATT = 0, M_P1, M_SP2, M_SB, M_P2, M_L0, M_L1, M_OUT };

// ---------------------------------------------------------------------------
__device__ __forceinline__ void gbar(unsigned target)
{
    __syncthreads();
    if (threadIdx.x == 0) {
        __threadfence();
        int sub = blockIdx.x & (NSUB - 1);
        unsigned subcnt = (GRID / NSUB) + ((sub < (GRID % NSUB)) ? 1u : 0u);
        if (atomicAdd(&g_cnt_sub[sub * 32], 1) == subcnt - 1) {
            g_cnt_sub[sub * 32] = 0;
            if (atomicAdd(&g_cnt_top, 1) == NSUB - 1) {
                g_cnt_top = 0;
                __threadfence();
                g_sense = target;
            }
        }
        while (g_sense != target) __nanosleep(32);
        __threadfence();
    }
    __syncthreads();
}

// ---------------------------------------------------------------------------
// unified double-buffered GEMM tile. 64m x 128j x chunk-k, 256 threads.
// ---------------------------------------------------------------------------
__device__ __noinline__ void gemm_tile(int mode, int jt, int s, int mt,
                                       const Ptrs& P,
                                       float (*Xs)[16][68], float (*Ws)[16][132])
{
    int K, chunk, J;
    const float* W;
    switch (mode) {
        case M_ATT: K = 512;  chunk = 48;  J = 256;   W = P.W_enc;  break;
        case M_P1:  K = 144;  chunk = 80;  J = 512;   W = P.W_p1;   break;
        case M_SP2: K = 256;  chunk = 64;  J = 512;   W = P.W_sp2;  break;
        case M_SB:  K = 64;   chunk = 64;  J = 256;   W = P.W_spkr; break;
        case M_P2:  K = 512;  chunk = 32;  J = 256;   W = P.W_p2;   break;
        case M_L0:  K = 832;  chunk = 80;  J = G3;    W = P.Wih0;   break;
        case M_L1:  K = 1024; chunk = 96;  J = G3;    W = P.Wih1;   break;
        default:    K = 1536; chunk = 48;  J = OUT_J; W = P.W_out;  break;
    }
    int lstm = (mode == M_L0 || mode == M_L1);
    int j0 = jt * 128, m0 = mt * 64;
    int kbeg = s * chunk;
    int kend = min(K, kbeg + chunk);
    int nsl  = (kend - kbeg) >> 4;

    int tid  = threadIdx.x;
    int mrow = tid >> 2;
    int kc   = (tid & 3) * 4;
    int mg   = m0 + mrow;

    const float* xrow = 0; float spd = 0.f;
    switch (mode) {
        case M_ATT: { int n = mg / 10; int t = mg - n * 10;
                      xrow = P.input_enc + ((size_t)n * T_ENC + t) * ENC; } break;
        case M_P1:  xrow = P.input_dec + mg * 80; break;
        case M_SP2: spd = P.speed[mg]; break;
        case M_SB:  xrow = P.spkr + mg * 64; break;
        case M_P2:  break;   // from p1 partials
        case M_L0:  xrow = g_inlstm + mg * IN_LSTM; break;
        case M_L1:  xrow = g_h1 + (size_t)mg * H4; break;
        default:    xrow = g_dec + (size_t)mg * DECCAT; break;
    }
    // W rows (lstm: skip dead f-gate rows: logical [1024,3072) -> phys +1024)
    int gj0 = j0 + mrow, gj1 = j0 + 64 + mrow;
    int jp0 = lstm ? (gj0 + (gj0 >= 1024 ? 1024 : 0)) : gj0;
    int jp1 = lstm ? (gj1 + (gj1 >= 1024 ? 1024 : 0)) : gj1;
    const float* wp0 = W + (size_t)jp0 * K;
    const float* wp1 = W + (size_t)jp1 * K;
    bool v0 = gj0 < J, v1 = gj1 < J;

    int warp = tid >> 5, lane = tid & 31;
    int mw = warp * 8;
    int j4 = lane * 4;
    u64 acc[4][4] = {};

    auto load_x = [&](int kg) -> float4 {
        float4 xv;
        if (mode == M_SP2) {
            float4 w1 = *(const float4*)(P.W_sp1 + kg);
            float4 b1 = *(const float4*)(P.b_sp1 + kg);
            xv.x = fmaxf(spd * w1.x + b1.x, 0.f);
            xv.y = fmaxf(spd * w1.y + b1.y, 0.f);
            xv.z = fmaxf(spd * w1.z + b1.z, 0.f);
            xv.w = fmaxf(spd * w1.w + b1.w, 0.f);
        } else if (mode == M_P1) {
            xv = (kg < 80) ? *(const float4*)(xrow + kg)
                           : *(const float4*)(P.spkr + mg * 64 + (kg - 80));
        } else if (mode == M_P2) {
            float4 bb = *(const float4*)(P.b_p1 + kg);
            float4 pa = __ldcg((const float4*)(g_p1_parts + (size_t)mg * 512 + kg));
            float4 pb = __ldcg((const float4*)(g_p1_parts + (size_t)(N_B + mg) * 512 + kg));
            xv.x = fmaxf(bb.x + pa.x + pb.x, 0.f);
            xv.y = fmaxf(bb.y + pa.y + pb.y, 0.f);
            xv.z = fmaxf(bb.z + pa.z + pb.z, 0.f);
            xv.w = fmaxf(bb.w + pa.w + pb.w, 0.f);
        } else if (mode == M_L0 || mode == M_L1 || mode == M_OUT) {
            xv = __ldcg((const float4*)(xrow + kg));
        } else {
            xv = *(const float4*)(xrow + kg);
        }
        return xv;
    };

    float4 xv = load_x(kbeg + kc);
    float4 wv0 = v0 ? *(const float4*)(wp0 + kbeg + kc) : make_float4(0, 0, 0, 0);
    float4 wv1 = v1 ? *(const float4*)(wp1 + kbeg + kc) : make_float4(0, 0, 0, 0);

    int buf = 0;
    for (int i = 0; i < nsl; i++) {
        Xs[buf][kc + 0][mrow] = xv.x; Xs[buf][kc + 1][mrow] = xv.y;
        Xs[buf][kc + 2][mrow] = xv.z; Xs[buf][kc + 3][mrow] = xv.w;
        Ws[buf][kc + 0][mrow] = wv0.x; Ws[buf][kc + 1][mrow] = wv0.y;
        Ws[buf][kc + 2][mrow] = wv0.z; Ws[buf][kc + 3][mrow] = wv0.w;
        Ws[buf][kc + 0][64 + mrow] = wv1.x; Ws[buf][kc + 1][64 + mrow] = wv1.y;
        Ws[buf][kc + 2][64 + mrow] = wv1.z; Ws[buf][kc + 3][64 + mrow] = wv1.w;
        __syncthreads();

        if (i + 1 < nsl) {
            int kg = kbeg + (i + 1) * 16 + kc;
            xv  = load_x(kg);
            wv0 = v0 ? *(const float4*)(wp0 + kg) : make_float4(0, 0, 0, 0);
            wv1 = v1 ? *(const float4*)(wp1 + kg) : make_float4(0, 0, 0, 0);
        }

        #pragma unroll
        for (int kk = 0; kk < 16; kk++) {
            ulonglong2 a01 = *(const ulonglong2*)&Xs[buf][kk][mw];
            ulonglong2 a23 = *(const ulonglong2*)&Xs[buf][kk][mw + 4];
            float4 w = *(const float4*)&Ws[buf][kk][j4];
            u64 w0, w1, w2, w3;
            DUP2(w0, w.x); DUP2(w1, w.y); DUP2(w2, w.z); DUP2(w3, w.w);
            FMA2(acc[0][0], a01.x, w0); FMA2(acc[0][1], a01.x, w1);
            FMA2(acc[0][2], a01.x, w2); FMA2(acc[0][3], a01.x, w3);
            FMA2(acc[1][0], a01.y, w0); FMA2(acc[1][1], a01.y, w1);
            FMA2(acc[1][2], a01.y, w2); FMA2(acc[1][3], a01.y, w3);
            FMA2(acc[2][0], a23.x, w0); FMA2(acc[2][1], a23.x, w1);
            FMA2(acc[2][2], a23.x, w2); FMA2(acc[2][3], a23.x, w3);
            FMA2(acc[3][0], a23.y, w0); FMA2(acc[3][1], a23.y, w1);
            FMA2(acc[3][2], a23.y, w2); FMA2(acc[3][3], a23.y, w3);
        }
        __syncthreads();
        buf ^= 1;
    }

    #pragma unroll
    for (int p = 0; p < 4; p++) {
        int r0 = m0 + mw + 2 * p;
        #pragma unroll
        for (int q = 0; q < 4; q++) {
            float vlo, vhi;
            UNPK(vlo, vhi, acc[p][q]);
            int jg = j0 + j4 + q;
            switch (mode) {
                case M_ATT: {
                    size_t base = ((size_t)s * 640 + r0) * ATT + jg;
                    g_att_parts[base] = vlo; g_att_parts[base + ATT] = vhi;
                } break;
                case M_P1: {
                    size_t base = ((size_t)s * N_B + r0) * 512 + jg;
                    g_p1_parts[base] = vlo; g_p1_parts[base + 512] = vhi;
                } break;
                case M_SP2: {
                    size_t base = ((size_t)s * N_B + r0) * 512 + jg;
                    g_sp2_parts[base] = vlo; g_sp2_parts[base + 512] = vhi;
                } break;
                case M_SB: {
                    g_sb[r0 * ATT + jg]       = vlo / (1.f + fabsf(vlo));
                    g_sb[(r0 + 1) * ATT + jg] = vhi / (1.f + fabsf(vhi));
                } break;
                case M_P2: {
                    size_t base = ((size_t)s * N_B + r0) * 256 + jg;
                    g_p2_parts[base] = vlo; g_p2_parts[base + 256] = vhi;
                } break;
                case M_OUT: {
                    if (jg < OUT_J) {
                        size_t base = ((size_t)s * N_B + r0) * OUT_J + jg;
                        g_out_parts[base] = vlo; g_out_parts[base + OUT_J] = vhi;
                    }
                } break;
                default: {   // L0 / L1
                    size_t base = ((size_t)s * N_B + r0) * G3 + jg;
                    g_lstm_parts[base] = vlo; g_lstm_parts[base + G3] = vhi;
                } break;
            }
        }
    }
}

// ---------------------------------------------------------------------------
__device__ void att_finish_dev(int n, const Ptrs& P)
{
    __shared__ float red[80];
    __shared__ float logit_s[NWIN];
    __shared__ float att_s[NWIN];

    int a = threadIdx.x;          // 256
    int warp = a >> 5, lane = a & 31;

    float sb    = __ldcg(&g_sb[n * ATT + a]);
    float spw   = P.speed[n] * P.W_speed_att[a];
    float wproj = P.W_proj[a];
    float be    = P.b_enc[a];

    float v[NWIN];
    #pragma unroll
    for (int t = 0; t < NWIN; t++) {
        float dot = be;
        #pragma unroll
        for (int s = 0; s < S_ATT; s++)
            dot += __ldcg(&g_att_parts[((size_t)s * 640 + n * 10 + t) * ATT + a]);
        float eb = dot / (1.f + fabsf(dot));
        float e  = eb + sb + P.conv_prev[a * 31 + (15 - t)] + spw;
        v[t] = tanhf(e) * wproj;
    }
    #pragma unroll
    for (int t = 0; t < NWIN; t++) {
        #pragma unroll
        for (int o = 16; o > 0; o >>= 1)
            v[t] += __shfl_xor_sync(0xffffffffu, v[t], o);
    }
    if (lane == 0) {
        #pragma unroll
        for (int t = 0; t < NWIN; t++) red[warp * NWIN + t] = v[t];
    }
    __syncthreads();
    if (a < NWIN) {
        float s = 0.f;
        #pragma unroll
        for (int w = 0; w < 8; w++) s += red[w * NWIN + a];
        logit_s[a] = s + P.b_proj[0];
    }
    __syncthreads();
    if (a == 0) {
        int len1 = max(P.lengths[n], 1) - 1;
        int hi = min(9, len1);
        float m = -1e30f;
        for (int t = 0; t <= hi; t++) m = fmaxf(m, logit_s[t]);
        float ss = 0.f;
        for (int t = 0; t < NWIN; t++) {
            float w = (t <= hi) ? expf(logit_s[t] - m) : 0.f;
            att_s[t] = w; ss += w;
        }
        float inv = 1.f / fmaxf(ss, 1e-12f);
        for (int t = 0; t < NWIN; t++) att_s[t] *= inv;
    }
    __syncthreads();

    for (int e = a; e < ENC; e += 256) {
        float spv = P.b_sp2[e];
        #pragma unroll
        for (int s = 0; s < S_SP2; s++)
            spv += __ldcg(&g_sp2_parts[((size_t)s * N_B + n) * 512 + e]);
        float c = tanhf(spv);
        #pragma unroll
        for (int t = 0; t < NWIN; t++)
            c += att_s[t] * P.input_enc[((size_t)n * T_ENC + t) * ENC + e];
        g_inlstm[n * IN_LSTM + 256 + e] = c;
        g_dec[(size_t)n * DECCAT + H4 + e] = c;
        if (P.write_ctx) P.ctx_out[n * ENC + e] = c;
    }
    if (a < 64) g_inlstm[n * IN_LSTM + 768 + a] = P.spkr[n * 64 + a];
}

// ---------------------------------------------------------------------------
// prenet2 finish: relu(bias + sum of 16 parts) -> g_inlstm cols [0,256)
__device__ void p2f_dev(const Ptrs& P)
{
    int idx = blockIdx.x * 256 + threadIdx.x;
    if (idx < N_B * 64) {
        int n = idx >> 6, u4 = (idx & 63) * 4;
        float4 a4 = *(const float4*)(P.b_p2 + u4);
        #pragma unroll
        for (int s = 0; s < S_P2; s++) {
            float4 pp = __ldcg((const float4*)(g_p2_parts + (size_t)(s * N_B + n) * 256 + u4));
            a4.x += pp.x; a4.y += pp.y; a4.z += pp.z; a4.w += pp.w;
        }
        float4 r;
        r.x = fmaxf(a4.x, 0.f); r.y = fmaxf(a4.y, 0.f);
        r.z = fmaxf(a4.z, 0.f); r.w = fmaxf(a4.w, 0.f);
        *(float4*)(g_inlstm + n * IN_LSTM + u4) = r;
    }
}

// ---------------------------------------------------------------------------
__device__ void act_dev(int layer, const Ptrs& P)
{
    const float* bih = layer ? P.bih1 : P.bih0;
    const float* bhh = layer ? P.bhh1 : P.bhh0;
    int idx = blockIdx.x * 256 + threadIdx.x;
    if (idx < N_B * 256) {
        int n = idx >> 8, u4 = (idx & 255) * 4;
        float gi[4], gg[4], go[4];
        {
            float4 a = *(const float4*)(bih + u4);
            float4 b = *(const float4*)(bhh + u4);
            gi[0] = a.x + b.x; gi[1] = a.y + b.y; gi[2] = a.z + b.z; gi[3] = a.w + b.w;
            a = *(const float4*)(bih + 2048 + u4);
            b = *(const float4*)(bhh + 2048 + u4);
            gg[0] = a.x + b.x; gg[1] = a.y + b.y; gg[2] = a.z + b.z; gg[3] = a.w + b.w;
            a = *(const float4*)(bih + 3072 + u4);
            b = *(const float4*)(bhh + 3072 + u4);
            go[0] = a.x + b.x; go[1] = a.y + b.y; go[2] = a.z + b.z; go[3] = a.w + b.w;
        }
        #pragma unroll
        for (int s = 0; s < S_L; s++) {
            const float* p = g_lstm_parts + ((size_t)s * N_B + n) * G3;
            float4 a = __ldcg((const float4*)(p + u4));
            float4 b = __ldcg((const float4*)(p + 1024 + u4));
            float4 c = __ldcg((const float4*)(p + 2048 + u4));
            gi[0] += a.x; gi[1] += a.y; gi[2] += a.z; gi[3] += a.w;
            gg[0] += b.x; gg[1] += b.y; gg[2] += b.z; gg[3] += b.w;
            go[0] += c.x; go[1] += c.y; go[2] += c.z; go[3] += c.w;
        }
        float4 h;
        float* hp = &h.x;
        #pragma unroll
        for (int q = 0; q < 4; q++) {
            float c = sigm(gi[q]) * tanhf(gg[q]);
            hp[q] = sigm(go[q]) * tanhf(c);
        }
        if (layer == 0) *(float4*)(g_h1 + n * H4 + u4) = h;
        else            *(float4*)(g_dec + (size_t)n * DECCAT + u4) = h;
    }
}

// ---------------------------------------------------------------------------
__global__ void __launch_bounds__(256, 2) fused_k(Ptrs P)
{
    __shared__ __align__(16) float Xs[2][16][68];
    __shared__ __align__(16) float Ws[2][16][132];

    unsigned s0 = 0;
    if (threadIdx.x == 0) s0 = g_sense;
    int b = blockIdx.x;

    // ---- stage A: ATT(220) + P1(8) + SP2(16) + SB(2) = 246 tasks ----
    if (b < 246) {
        int mode, jt, s = 0, mt = 0;
        if (b < 220)      { mode = M_ATT; jt = b & 1; int r = b >> 1; s = r % 11; mt = r / 11; }
        else if (b < 228) { int t = b - 220; mode = M_P1;  jt = t & 3; s = t >> 2; }
        else if (b < 244) { int t = b - 228; mode = M_SP2; jt = t & 3; s = t >> 2; }
        else              { mode = M_SB;  jt = b - 244; }
        gemm_tile(mode, jt, s, mt, P, Xs, Ws);
    }
    gbar(s0 + 1);

    // ---- stage B: att_finish(64) + P2 GEMM(32) ----
    if (b < 64) att_finish_dev(b, P);
    else if (b < 96) { int t = b - 64; gemm_tile(M_P2, t & 1, t >> 1, 0, P, Xs, Ws); }
    gbar(s0 + 2);

    // ---- stage B2: prenet2 finish -> g_inlstm[0,256) ----
    p2f_dev(P);
    gbar(s0 + 3);

    // ---- stage C: LSTM0 GEMM (24 jt x 11 s = 264) ----
    if (b < 264) gemm_tile(M_L0, b % 24, b / 24, 0, P, Xs, Ws);
    gbar(s0 + 4);

    // ---- stage D: LSTM0 activation ----
    act_dev(0, P);
    gbar(s0 + 5);

    // ---- stage E: LSTM1 GEMM (24 jt x 11 s = 264) ----
    if (b < 264) gemm_tile(M_L1, b % 24, b / 24, 0, P, Xs, Ws);
    gbar(s0 + 6);

    // ---- stage F: LSTM1 activation ----
    act_dev(1, P);
    gbar(s0 + 7);

    // ---- stage G: output GEMM (2 jt x 32 s = 64) ----
    if (b < 64) gemm_tile(M_OUT, b & 1, b >> 1, 0, P, Xs, Ws);
    gbar(s0 + 8);

    // ---- stage H: output reduction ----
    int gt = b * 256 + threadIdx.x;
    if (gt < N_B * OUT_J) {
        int n = gt / OUT_J, j = gt - n * OUT_J;
        float a = P.b_out[j];
        #pragma unroll
        for (int s = 0; s < S_OUT; s++)
            a += __ldcg(&g_out_parts[((size_t)s * N_B + n) * OUT_J + j]);
        P.out[n * OUT_J + j] = a;
    }
}

// ---------------------------------------------------------------------------
extern "C" void kernel_launch(void* const* d_in, const int* in_sizes, int n_in,
                              void* d_out, int out_size)
{
    Ptrs P;
    P.input_enc   = (const float*)d_in[0];
    P.input_dec   = (const float*)d_in[1];
    P.spkr        = (const float*)d_in[2];
    P.lengths     = (const int*)  d_in[3];
    P.speed       = (const float*)d_in[4];
    P.W_enc       = (const float*)d_in[5];
    P.b_enc       = (const float*)d_in[6];
    P.W_spkr      = (const float*)d_in[7];
    P.conv_prev   = (const float*)d_in[8];
    P.W_speed_att = (const float*)d_in[9];
    P.W_proj      = (const float*)d_in[10];
    P.b_proj      = (const float*)d_in[11];
    P.W_sp1       = (const float*)d_in[12];
    P.b_sp1       = (const float*)d_in[13];
    P.W_sp2       = (const float*)d_in[14];
    P.b_sp2       = (const float*)d_in[15];
    P.W_p1        = (const float*)d_in[16];
    P.b_p1        = (const float*)d_in[17];
    P.W_p2        = (const float*)d_in[18];
    P.b_p2        = (const float*)d_in[19];
    P.Wih0        = (const float*)d_in[20];
    P.bih0        = (const float*)d_in[22];
    P.bhh0        = (const float*)d_in[23];
    P.Wih1        = (const float*)d_in[24];
    P.bih1        = (const float*)d_in[26];
    P.bhh1        = (const float*)d_in[27];
    P.W_out       = (const float*)d_in[28];
    P.b_out       = (const float*)d_in[29];

    float* out = (float*)d_out;
    P.out = out;
    P.write_ctx = (out_size >= N_B * 2 * 80 + N_B * ENC) ? 1 : 0;
    P.ctx_out = out + N_B * 2 * 80;

    fused_k<<<GRID, 256>>>(P);
}

// round 8
// speedup vs baseline: 1.1482x; 1.1482x over previous
#include <cuda_runtime.h>
#include <math.h>
#include <stddef.h>

// ---------------------------------------------------------------------------
// AttnDecoderRNN2 single step, algebraically reduced (validated):
//  * attention window always t in [0,9]; softmax max cancels in L1 norm
//  * zero LSTM state -> Whh unused, f-gate dead (i,g,o rows only: J=3072)
// Round 7: revert to 148 blocks / 1 per SM (round-6 occupancy experiment
// regressed). Monotonic two-level grid barrier (~0.5us vs ~2.3us); single
// __syncthreads per k-slice (the post-compute sync was redundant).
// ---------------------------------------------------------------------------

#define GRID    148
#define N_B     64
#define T_ENC   2000
#define ENC     512
#define ATT     256
#define H4      1024
#define G3      3072
#define IN_LSTM 832
#define DECCAT  1536
#define NWIN    10
#define OUT_J   160

#define S_ATT 6
#define S_SP2 4
#define S_P2  8
#define S_L   6
#define S_OUT 32
#define NSUB  16

typedef unsigned long long u64;

// scratch (device globals; allocation forbidden)
__device__ __align__(16) float g_att_parts[S_ATT * 640 * ATT];
__device__ __align__(16) float g_p1_parts [2 * N_B * 512];
__device__ __align__(16) float g_sp2_parts[S_SP2 * N_B * 512];
__device__ __align__(16) float g_p2_parts [S_P2 * N_B * 256];
__device__ __align__(16) float g_sb       [N_B * ATT];
__device__ __align__(16) float g_lstm_parts[S_L * N_B * G3];
__device__ __align__(16) float g_out_parts[S_OUT * N_B * OUT_J];
__device__ __align__(16) float g_inlstm   [N_B * IN_LSTM];
__device__ __align__(16) float g_h1       [N_B * H4];
__device__ __align__(16) float g_dec      [N_B * DECCAT];    // [h2 | context]

// monotonic two-level grid barrier (counters never reset -> no reset race)
__device__ unsigned g_cnt_sub[NSUB * 32];   // padded to 128B apart
__device__ unsigned g_cnt_top = 0;
__device__ volatile unsigned g_sense = 0;

struct Ptrs {
    const float *input_enc, *input_dec, *spkr, *speed;
    const float *W_enc, *b_enc, *W_spkr, *conv_prev, *W_speed_att, *W_proj, *b_proj;
    const float *W_sp1, *b_sp1, *W_sp2, *b_sp2;
    const float *W_p1, *b_p1, *W_p2, *b_p2;
    const float *Wih0, *bih0, *bhh0, *Wih1, *bih1, *bhh1, *W_out, *b_out;
    const int *lengths;
    float *out, *ctx_out;
    int write_ctx;
};

__device__ __forceinline__ float sigm(float x) { return 1.f / (1.f + expf(-x)); }

#define FMA2(d, a, b) asm("fma.rn.f32x2 %0,%1,%2,%0;" : "+l"(d) : "l"(a), "l"(b))
#define DUP2(d, s)    asm("mov.b64 %0,{%1,%1};" : "=l"(d) : "f"(s))
#define UNPK(lo, hi, v) asm("mov.b64 {%0,%1},%2;" : "=f"(lo), "=f"(hi) : "l"(v))

enum { M_ATT = 0, M_P1, M_SP2, M_SB, M_P2, M_L0, M_L1, M_OUT };

// ---------------------------------------------------------------------------
// target is the global barrier index (monotonic across graph replays):
// after barrier #target completes, each sub-counter == target * subcnt.
// Only threadIdx.x==0 uses target (others pass garbage).
// ---------------------------------------------------------------------------
__device__ __forceinline__ void gbar(unsigned target)
{
    __syncthreads();
    if (threadIdx.x == 0) {
        __threadfence();
        unsigned sub = blockIdx.x & (NSUB - 1);
        unsigned subcnt = (GRID / NSUB) + ((sub < (GRID & (NSUB - 1))) ? 1u : 0u);
        if (atomicAdd(&g_cnt_sub[sub * 32], 1u) == target * subcnt - 1u) {
            if (atomicAdd(&g_cnt_top, 1u) == target * NSUB - 1u) {
                __threadfence();
                g_sense = target;
            }
        }
        while (g_sense < target) __nanosleep(20);
        __threadfence();
    }
    __syncthreads();
}

// ---------------------------------------------------------------------------
// unified double-buffered GEMM tile. 64m x 128j x chunk-k, 256 threads.
// ONE __syncthreads per slice (store->sync->prefetch->compute).
// ---------------------------------------------------------------------------
__device__ __noinline__ void gemm_tile(int mode, int jt, int s, int mt,
                                       const Ptrs& P,
                                       float (*Xs)[16][68], float (*Ws)[16][132])
{
    int K, chunk, J;
    const float* W;
    switch (mode) {
        case M_ATT: K = 512;  chunk = 96;  J = 256;   W = P.W_enc;  break;
        case M_P1:  K = 144;  chunk = 80;  J = 512;   W = P.W_p1;   break;
        case M_SP2: K = 256;  chunk = 64;  J = 512;   W = P.W_sp2;  break;
        case M_SB:  K = 64;   chunk = 64;  J = 256;   W = P.W_spkr; break;
        case M_P2:  K = 512;  chunk = 64;  J = 256;   W = P.W_p2;   break;
        case M_L0:  K = 832;  chunk = 144; J = G3;    W = P.Wih0;   break;
        case M_L1:  K = 1024; chunk = 176; J = G3;    W = P.Wih1;   break;
        default:    K = 1536; chunk = 48;  J = OUT_J; W = P.W_out;  break;
    }
    int lstm = (mode == M_L0 || mode == M_L1);
    int j0 = jt * 128, m0 = mt * 64;
    int kbeg = s * chunk;
    int kend = min(K, kbeg + chunk);
    int nsl  = (kend - kbeg) >> 4;

    int tid  = threadIdx.x;
    int mrow = tid >> 2;
    int kc   = (tid & 3) * 4;
    int mg   = m0 + mrow;

    const float* xrow = 0; float spd = 0.f;
    switch (mode) {
        case M_ATT: { int n = mg / 10; int t = mg - n * 10;
                      xrow = P.input_enc + ((size_t)n * T_ENC + t) * ENC; } break;
        case M_P1:  xrow = P.input_dec + mg * 80; break;
        case M_SP2: spd = P.speed[mg]; break;
        case M_SB:  xrow = P.spkr + mg * 64; break;
        case M_P2:  break;   // from p1 partials
        case M_L0:  xrow = g_inlstm + mg * IN_LSTM; break;
        case M_L1:  xrow = g_h1 + (size_t)mg * H4; break;
        default:    xrow = g_dec + (size_t)mg * DECCAT; break;
    }
    // W rows (lstm: skip dead f-gate rows: logical [1024,3072) -> phys +1024)
    int gj0 = j0 + mrow, gj1 = j0 + 64 + mrow;
    int jp0 = lstm ? (gj0 + (gj0 >= 1024 ? 1024 : 0)) : gj0;
    int jp1 = lstm ? (gj1 + (gj1 >= 1024 ? 1024 : 0)) : gj1;
    const float* wp0 = W + (size_t)jp0 * K;
    const float* wp1 = W + (size_t)jp1 * K;
    bool v0 = gj0 < J, v1 = gj1 < J;

    int warp = tid >> 5, lane = tid & 31;
    int mw = warp * 8;
    int j4 = lane * 4;
    u64 acc[4][4] = {};

    auto load_x = [&](int kg) -> float4 {
        float4 xv;
        if (mode == M_SP2) {
            float4 w1 = *(const float4*)(P.W_sp1 + kg);
            float4 b1 = *(const float4*)(P.b_sp1 + kg);
            xv.x = fmaxf(spd * w1.x + b1.x, 0.f);
            xv.y = fmaxf(spd * w1.y + b1.y, 0.f);
            xv.z = fmaxf(spd * w1.z + b1.z, 0.f);
            xv.w = fmaxf(spd * w1.w + b1.w, 0.f);
        } else if (mode == M_P1) {
            xv = (kg < 80) ? *(const float4*)(xrow + kg)
                           : *(const float4*)(P.spkr + mg * 64 + (kg - 80));
        } else if (mode == M_P2) {
            float4 bb = *(const float4*)(P.b_p1 + kg);
            float4 pa = __ldcg((const float4*)(g_p1_parts + (size_t)mg * 512 + kg));
            float4 pb = __ldcg((const float4*)(g_p1_parts + (size_t)(N_B + mg) * 512 + kg));
            xv.x = fmaxf(bb.x + pa.x + pb.x, 0.f);
            xv.y = fmaxf(bb.y + pa.y + pb.y, 0.f);
            xv.z = fmaxf(bb.z + pa.z + pb.z, 0.f);
            xv.w = fmaxf(bb.w + pa.w + pb.w, 0.f);
        } else if (mode == M_L0 || mode == M_L1 || mode == M_OUT) {
            xv = __ldcg((const float4*)(xrow + kg));
        } else {
            xv = *(const float4*)(xrow + kg);
        }
        return xv;
    };

    float4 xv = load_x(kbeg + kc);
    float4 wv0 = v0 ? *(const float4*)(wp0 + kbeg + kc) : make_float4(0, 0, 0, 0);
    float4 wv1 = v1 ? *(const float4*)(wp1 + kbeg + kc) : make_float4(0, 0, 0, 0);

    int buf = 0;
    for (int i = 0; i < nsl; i++) {
        Xs[buf][kc + 0][mrow] = xv.x; Xs[buf][kc + 1][mrow] = xv.y;
        Xs[buf][kc + 2][mrow] = xv.z; Xs[buf][kc + 3][mrow] = xv.w;
        Ws[buf][kc + 0][mrow] = wv0.x; Ws[buf][kc + 1][mrow] = wv0.y;
        Ws[buf][kc + 2][mrow] = wv0.z; Ws[buf][kc + 3][mrow] = wv0.w;
        Ws[buf][kc + 0][64 + mrow] = wv1.x; Ws[buf][kc + 1][64 + mrow] = wv1.y;
        Ws[buf][kc + 2][64 + mrow] = wv1.z; Ws[buf][kc + 3][64 + mrow] = wv1.w;
        __syncthreads();

        if (i + 1 < nsl) {
            int kg = kbeg + (i + 1) * 16 + kc;
            xv  = load_x(kg);
            wv0 = v0 ? *(const float4*)(wp0 + kg) : make_float4(0, 0, 0, 0);
            wv1 = v1 ? *(const float4*)(wp1 + kg) : make_float4(0, 0, 0, 0);
        }

        #pragma unroll
        for (int kk = 0; kk < 16; kk++) {
            ulonglong2 a01 = *(const ulonglong2*)&Xs[buf][kk][mw];
            ulonglong2 a23 = *(const ulonglong2*)&Xs[buf][kk][mw + 4];
            float4 w = *(const float4*)&Ws[buf][kk][j4];
            u64 w0, w1, w2, w3;
            DUP2(w0, w.x); DUP2(w1, w.y); DUP2(w2, w.z); DUP2(w3, w.w);
            FMA2(acc[0][0], a01.x, w0); FMA2(acc[0][1], a01.x, w1);
            FMA2(acc[0][2], a01.x, w2); FMA2(acc[0][3], a01.x, w3);
            FMA2(acc[1][0], a01.y, w0); FMA2(acc[1][1], a01.y, w1);
            FMA2(acc[1][2], a01.y, w2); FMA2(acc[1][3], a01.y, w3);
            FMA2(acc[2][0], a23.x, w0); FMA2(acc[2][1], a23.x, w1);
            FMA2(acc[2][2], a23.x, w2); FMA2(acc[2][3], a23.x, w3);
            FMA2(acc[3][0], a23.y, w0); FMA2(acc[3][1], a23.y, w1);
            FMA2(acc[3][2], a23.y, w2); FMA2(acc[3][3], a23.y, w3);
        }
        buf ^= 1;
    }

    #pragma unroll
    for (int p = 0; p < 4; p++) {
        int r0 = m0 + mw + 2 * p;
        #pragma unroll
        for (int q = 0; q < 4; q++) {
            float vlo, vhi;
            UNPK(vlo, vhi, acc[p][q]);
            int jg = j0 + j4 + q;
            switch (mode) {
                case M_ATT: {
                    size_t base = ((size_t)s * 640 + r0) * ATT + jg;
                    g_att_parts[base] = vlo; g_att_parts[base + ATT] = vhi;
                } break;
                case M_P1: {
                    size_t base = ((size_t)s * N_B + r0) * 512 + jg;
                    g_p1_parts[base] = vlo; g_p1_parts[base + 512] = vhi;
                } break;
                case M_SP2: {
                    size_t base = ((size_t)s * N_B + r0) * 512 + jg;
                    g_sp2_parts[base] = vlo; g_sp2_parts[base + 512] = vhi;
                } break;
                case M_SB: {
                    g_sb[r0 * ATT + jg]       = vlo / (1.f + fabsf(vlo));
                    g_sb[(r0 + 1) * ATT + jg] = vhi / (1.f + fabsf(vhi));
                } break;
                case M_P2: {
                    size_t base = ((size_t)s * N_B + r0) * 256 + jg;
                    g_p2_parts[base] = vlo; g_p2_parts[base + 256] = vhi;
                } break;
                case M_OUT: {
                    if (jg < OUT_J) {
                        size_t base = ((size_t)s * N_B + r0) * OUT_J + jg;
                        g_out_parts[base] = vlo; g_out_parts[base + OUT_J] = vhi;
                    }
                } break;
                default: {   // L0 / L1
                    size_t base = ((size_t)s * N_B + r0) * G3 + jg;
                    g_lstm_parts[base] = vlo; g_lstm_parts[base + G3] = vhi;
                } break;
            }
        }
    }
}

// ---------------------------------------------------------------------------
__device__ void att_finish_dev(int n, const Ptrs& P)
{
    __shared__ float red[80];
    __shared__ float logit_s[NWIN];
    __shared__ float att_s[NWIN];

    int a = threadIdx.x;          // 256
    int warp = a >> 5, lane = a & 31;

    float sb    = __ldcg(&g_sb[n * ATT + a]);
    float spw   = P.speed[n] * P.W_speed_att[a];
    float wproj = P.W_proj[a];
    float be    = P.b_enc[a];

    float v[NWIN];
    #pragma unroll
    for (int t = 0; t < NWIN; t++) {
        float dot = be;
        #pragma unroll
        for (int s = 0; s < S_ATT; s++)
            dot += __ldcg(&g_att_parts[((size_t)s * 640 + n * 10 + t) * ATT + a]);
        float eb = dot / (1.f + fabsf(dot));
        float e  = eb + sb + P.conv_prev[a * 31 + (15 - t)] + spw;
        v[t] = tanhf(e) * wproj;
    }
    #pragma unroll
    for (int t = 0; t < NWIN; t++) {
        #pragma unroll
        for (int o = 16; o > 0; o >>= 1)
            v[t] += __shfl_xor_sync(0xffffffffu, v[t], o);
    }
    if (lane == 0) {
        #pragma unroll
        for (int t = 0; t < NWIN; t++) red[warp * NWIN + t] = v[t];
    }
    __syncthreads();
    if (a < NWIN) {
        float s = 0.f;
        #pragma unroll
        for (int w = 0; w < 8; w++) s += red[w * NWIN + a];
        logit_s[a] = s + P.b_proj[0];
    }
    __syncthreads();
    if (a == 0) {
        int len1 = max(P.lengths[n], 1) - 1;
        int hi = min(9, len1);
        float m = -1e30f;
        for (int t = 0; t <= hi; t++) m = fmaxf(m, logit_s[t]);
        float ss = 0.f;
        for (int t = 0; t < NWIN; t++) {
            float w = (t <= hi) ? expf(logit_s[t] - m) : 0.f;
            att_s[t] = w; ss += w;
        }
        float inv = 1.f / fmaxf(ss, 1e-12f);
        for (int t = 0; t < NWIN; t++) att_s[t] *= inv;
    }
    __syncthreads();

    for (int e = a; e < ENC; e += 256) {
        float spv = P.b_sp2[e];
        #pragma unroll
        for (int s = 0; s < S_SP2; s++)
            spv += __ldcg(&g_sp2_parts[((size_t)s * N_B + n) * 512 + e]);
        float c = tanhf(spv);
        #pragma unroll
        for (int t = 0; t < NWIN; t++)
            c += att_s[t] * P.input_enc[((size_t)n * T_ENC + t) * ENC + e];
        g_inlstm[n * IN_LSTM + 256 + e] = c;
        g_dec[(size_t)n * DECCAT + H4 + e] = c;
        if (P.write_ctx) P.ctx_out[n * ENC + e] = c;
    }
    if (a < 64) g_inlstm[n * IN_LSTM + 768 + a] = P.spkr[n * 64 + a];
}

// ---------------------------------------------------------------------------
// prenet2 finish: relu(bias + sum of parts) -> g_inlstm cols [0,256)
__device__ void p2f_dev(const Ptrs& P)
{
    int idx = blockIdx.x * 256 + threadIdx.x;
    if (idx < N_B * 64) {
        int n = idx >> 6, u4 = (idx & 63) * 4;
        float4 a4 = *(const float4*)(P.b_p2 + u4);
        #pragma unroll
        for (int s = 0; s < S_P2; s++) {
            float4 pp = __ldcg((const float4*)(g_p2_parts + (size_t)(s * N_B + n) * 256 + u4));
            a4.x += pp.x; a4.y += pp.y; a4.z += pp.z; a4.w += pp.w;
        }
        float4 r;
        r.x = fmaxf(a4.x, 0.f); r.y = fmaxf(a4.y, 0.f);
        r.z = fmaxf(a4.z, 0.f); r.w = fmaxf(a4.w, 0.f);
        *(float4*)(g_inlstm + n * IN_LSTM + u4) = r;
    }
}

// ---------------------------------------------------------------------------
__device__ void act_dev(int layer, const Ptrs& P)
{
    const float* bih = layer ? P.bih1 : P.bih0;
    const float* bhh = layer ? P.bhh1 : P.bhh0;
    int idx = blockIdx.x * 256 + threadIdx.x;
    if (idx < N_B * 256) {
        int n = idx >> 8, u4 = (idx & 255) * 4;
        float gi[4], gg[4], go[4];
        {
            float4 a = *(const float4*)(bih + u4);
            float4 b = *(const float4*)(bhh + u4);
            gi[0] = a.x + b.x; gi[1] = a.y + b.y; gi[2] = a.z + b.z; gi[3] = a.w + b.w;
            a = *(const float4*)(bih + 2048 + u4);
            b = *(const float4*)(bhh + 2048 + u4);
            gg[0] = a.x + b.x; gg[1] = a.y + b.y; gg[2] = a.z + b.z; gg[3] = a.w + b.w;
            a = *(const float4*)(bih + 3072 + u4);
            b = *(const float4*)(bhh + 3072 + u4);
            go[0] = a.x + b.x; go[1] = a.y + b.y; go[2] = a.z + b.z; go[3] = a.w + b.w;
        }
        #pragma unroll
        for (int s = 0; s < S_L; s++) {
            const float* p = g_lstm_parts + ((size_t)s * N_B + n) * G3;
            float4 a = __ldcg((const float4*)(p + u4));
            float4 b = __ldcg((const float4*)(p + 1024 + u4));
            float4 c = __ldcg((const float4*)(p + 2048 + u4));
            gi[0] += a.x; gi[1] += a.y; gi[2] += a.z; gi[3] += a.w;
            gg[0] += b.x; gg[1] += b.y; gg[2] += b.z; gg[3] += b.w;
            go[0] += c.x; go[1] += c.y; go[2] += c.z; go[3] += c.w;
        }
        float4 h;
        float* hp = &h.x;
        #pragma unroll
        for (int q = 0; q < 4; q++) {
            float c = sigm(gi[q]) * tanhf(gg[q]);
            hp[q] = sigm(go[q]) * tanhf(c);
        }
        if (layer == 0) *(float4*)(g_h1 + n * H4 + u4) = h;
        else            *(float4*)(g_dec + (size_t)n * DECCAT + u4) = h;
    }
}

// ---------------------------------------------------------------------------
__global__ void __launch_bounds__(256, 1) fused_k(Ptrs P)
{
    __shared__ __align__(16) float Xs[2][16][68];
    __shared__ __align__(16) float Ws[2][16][132];

    unsigned s0 = 0;
    if (threadIdx.x == 0) s0 = g_sense;
    int b = blockIdx.x;

    // ---- stage A: ATT(120) + P1(8) + SP2(16) + SB(2) = 146 tasks ----
    if (b < 146) {
        int mode, jt, s = 0, mt = 0;
        if (b < 120)      { mode = M_ATT; jt = b & 1; int r = b >> 1; s = r % 6; mt = r / 6; }
        else if (b < 128) { int t = b - 120; mode = M_P1;  jt = t & 3; s = t >> 2; }
        else if (b < 144) { int t = b - 128; mode = M_SP2; jt = t & 3; s = t >> 2; }
        else              { mode = M_SB;  jt = b - 144; }
        gemm_tile(mode, jt, s, mt, P, Xs, Ws);
    }
    gbar(s0 + 1);

    // ---- stage B: att_finish(64) + P2 GEMM(16) ----
    if (b < 64) att_finish_dev(b, P);
    else if (b < 80) { int t = b - 64; gemm_tile(M_P2, t & 1, t >> 1, 0, P, Xs, Ws); }
    gbar(s0 + 2);

    // ---- stage B2: prenet2 finish -> g_inlstm[0,256) ----
    p2f_dev(P);
    gbar(s0 + 3);

    // ---- stage C: LSTM0 GEMM (24 jt x 6 s = 144) ----
    if (b < 144) gemm_tile(M_L0, b % 24, b / 24, 0, P, Xs, Ws);
    gbar(s0 + 4);

    // ---- stage D: LSTM0 activation ----
    act_dev(0, P);
    gbar(s0 + 5);

    // ---- stage E: LSTM1 GEMM (24 jt x 6 s = 144) ----
    if (b < 144) gemm_tile(M_L1, b % 24, b / 24, 0, P, Xs, Ws);
    gbar(s0 + 6);

    // ---- stage F: LSTM1 activation ----
    act_dev(1, P);
    gbar(s0 + 7);

    // ---- stage G: output GEMM (2 jt x 32 s = 64) ----
    if (b < 64) gemm_tile(M_OUT, b & 1, b >> 1, 0, P, Xs, Ws);
    gbar(s0 + 8);

    // ---- stage H: output reduction ----
    int gt = b * 256 + threadIdx.x;
    if (gt < N_B * OUT_J) {
        int n = gt / OUT_J, j = gt - n * OUT_J;
        float a = P.b_out[j];
        #pragma unroll
        for (int s = 0; s < S_OUT; s++)
            a += __ldcg(&g_out_parts[((size_t)s * N_B + n) * OUT_J + j]);
        P.out[n * OUT_J + j] = a;
    }
}

// ---------------------------------------------------------------------------
extern "C" void kernel_launch(void* const* d_in, const int* in_sizes, int n_in,
                              void* d_out, int out_size)
{
    Ptrs P;
    P.input_enc   = (const float*)d_in[0];
    P.input_dec   = (const float*)d_in[1];
    P.spkr        = (const float*)d_in[2];
    P.lengths     = (const int*)  d_in[3];
    P.speed       = (const float*)d_in[4];
    P.W_enc       = (const float*)d_in[5];
    P.b_enc       = (const float*)d_in[6];
    P.W_spkr      = (const float*)d_in[7];
    P.conv_prev   = (const float*)d_in[8];
    P.W_speed_att = (const float*)d_in[9];
    P.W_proj      = (const float*)d_in[10];
    P.b_proj      = (const float*)d_in[11];
    P.W_sp1       = (const float*)d_in[12];
    P.b_sp1       = (const float*)d_in[13];
    P.W_sp2       = (const float*)d_in[14];
    P.b_sp2       = (const float*)d_in[15];
    P.W_p1        = (const float*)d_in[16];
    P.b_p1        = (const float*)d_in[17];
    P.W_p2        = (const float*)d_in[18];
    P.b_p2        = (const float*)d_in[19];
    P.Wih0        = (const float*)d_in[20];
    P.bih0        = (const float*)d_in[22];
    P.bhh0        = (const float*)d_in[23];
    P.Wih1        = (const float*)d_in[24];
    P.bih1        = (const float*)d_in[26];
    P.bhh1        = (const float*)d_in[27];
    P.W_out       = (const float*)d_in[28];
    P.b_out       = (const float*)d_in[29];

    float* out = (float*)d_out;
    P.out = out;
    P.write_ctx = (out_size >= N_B * 2 * 80 + N_B * ENC) ? 1 : 0;
    P.ctx_out = out + N_B * 2 * 80;

    fused_k<<<GRID, 256>>>(P);
}

// round 9
// speedup vs baseline: 1.1576x; 1.0081x over previous
#include <cuda_runtime.h>
#include <math.h>
#include <stddef.h>

// ---------------------------------------------------------------------------
// AttnDecoderRNN2 single step, algebraically reduced (validated):
//  * attention window always t in [0,9]; softmax max cancels in L1 norm
//  * zero LSTM state -> Whh unused, f-gate dead (i,g,o rows only: J=3072)
// Round 8: 512 threads/block (4 warps/SMSP) with UNCHANGED task/chunk
// structure (148 blocks, round-5 chunking) -> clean latency-hiding test.
// Per-thread fragment 4m x 4j; float4 epilogue stores; 7 barriers.
// ---------------------------------------------------------------------------

#define GRID    148
#define NTHR    512
#define N_B     64
#define T_ENC   2000
#define ENC     512
#define ATT     256
#define H4      1024
#define G3      3072
#define IN_LSTM 832
#define DECCAT  1536
#define NWIN    10
#define OUT_J   160

#define S_ATT 6
#define S_SP2 4
#define S_P2  8
#define S_L   6
#define S_OUT 32
#define NSUB  16

typedef unsigned long long u64;

// scratch (device globals; allocation forbidden)
__device__ __align__(16) float g_att_parts[S_ATT * 640 * ATT];
__device__ __align__(16) float g_p1_parts [2 * N_B * 512];
__device__ __align__(16) float g_sp2_parts[S_SP2 * N_B * 512];
__device__ __align__(16) float g_p2_parts [S_P2 * N_B * 256];
__device__ __align__(16) float g_sb       [N_B * ATT];
__device__ __align__(16) float g_lstm_parts[S_L * N_B * G3];
__device__ __align__(16) float g_out_parts[S_OUT * N_B * OUT_J];
__device__ __align__(16) float g_inlstm   [N_B * IN_LSTM];
__device__ __align__(16) float g_h1       [N_B * H4];
__device__ __align__(16) float g_dec      [N_B * DECCAT];    // [h2 | context]

// monotonic two-level grid barrier
__device__ unsigned g_cnt_sub[NSUB * 32];   // padded 128B apart
__device__ unsigned g_cnt_top = 0;
__device__ volatile unsigned g_sense = 0;

struct Ptrs {
    const float *input_enc, *input_dec, *spkr, *speed;
    const float *W_enc, *b_enc, *W_spkr, *conv_prev, *W_speed_att, *W_proj, *b_proj;
    const float *W_sp1, *b_sp1, *W_sp2, *b_sp2;
    const float *W_p1, *b_p1, *W_p2, *b_p2;
    const float *Wih0, *bih0, *bhh0, *Wih1, *bih1, *bhh1, *W_out, *b_out;
    const int *lengths;
    float *out, *ctx_out;
    int write_ctx;
};

__device__ __forceinline__ float sigm(float x) { return 1.f / (1.f + expf(-x)); }

#define FMA2(d, a, b) asm("fma.rn.f32x2 %0,%1,%2,%0;" : "+l"(d) : "l"(a), "l"(b))
#define DUP2(d, s)    asm("mov.b64 %0,{%1,%1};" : "=l"(d) : "f"(s))
#define UNPK(lo, hi, v) asm("mov.b64 {%0,%1},%2;" : "=f"(lo), "=f"(hi) : "l"(v))

enum { M_ATT = 0, M_P1, M_SP2, M_SB, M_P2, M_L0, M_L1, M_OUT };

// ---------------------------------------------------------------------------
__device__ __forceinline__ void gbar(unsigned target)
{
    __syncthreads();
    if (threadIdx.x == 0) {
        __threadfence();
        unsigned sub = blockIdx.x & (NSUB - 1);
        unsigned subcnt = (GRID / NSUB) + ((sub < (GRID & (NSUB - 1))) ? 1u : 0u);
        if (atomicAdd(&g_cnt_sub[sub * 32], 1u) == target * subcnt - 1u) {
            if (atomicAdd(&g_cnt_top, 1u) == target * NSUB - 1u) {
                __threadfence();
                g_sense = target;
            }
        }
        while (g_sense < target) __nanosleep(20);
        __threadfence();
    }
    __syncthreads();
}

// ---------------------------------------------------------------------------
// double-buffered GEMM tile, 512 threads. Tile 64m x 128j x chunk-k.
// Per-thread fragment 4m x 4j (8 FMA2 per kk). W rows loaded by all 16
// warps (one float4 each); X rows by threads < 256.
// ---------------------------------------------------------------------------
__device__ __noinline__ void gemm_tile(int mode, int jt, int s, int mt,
                                       const Ptrs& P,
                                       float (*Xs)[16][68], float (*Ws)[16][132])
{
    int K, chunk, J;
    const float* W;
    switch (mode) {
        case M_ATT: K = 512;  chunk = 96;  J = 256;   W = P.W_enc;  break;
        case M_P1:  K = 144;  chunk = 80;  J = 512;   W = P.W_p1;   break;
        case M_SP2: K = 256;  chunk = 64;  J = 512;   W = P.W_sp2;  break;
        case M_SB:  K = 64;   chunk = 64;  J = 256;   W = P.W_spkr; break;
        case M_P2:  K = 512;  chunk = 64;  J = 256;   W = P.W_p2;   break;
        case M_L0:  K = 832;  chunk = 144; J = G3;    W = P.Wih0;   break;
        case M_L1:  K = 1024; chunk = 176; J = G3;    W = P.Wih1;   break;
        default:    K = 1536; chunk = 48;  J = OUT_J; W = P.W_out;  break;
    }
    int lstm = (mode == M_L0 || mode == M_L1);
    int j0 = jt * 128, m0 = mt * 64;
    int kbeg = s * chunk;
    int kend = min(K, kbeg + chunk);
    int nsl  = (kend - kbeg) >> 4;

    int tid  = threadIdx.x;
    int wrow = tid >> 2;          // 0..127: W row within j-tile
    int kc   = (tid & 3) * 4;
    int mrow = wrow;              // X row (only tid < 256)
    int mg   = m0 + mrow;
    bool xldr = tid < 256;

    const float* xrow = 0; const float *p2a = 0, *p2b = 0; float spd = 0.f;
    if (xldr) switch (mode) {
        case M_ATT: { int n = mg / 10; int t = mg - n * 10;
                      xrow = P.input_enc + ((size_t)n * T_ENC + t) * ENC; } break;
        case M_P1:  xrow = P.input_dec + mg * 80; break;
        case M_SP2: spd = P.speed[mg]; break;
        case M_SB:  xrow = P.spkr + mg * 64; break;
        case M_P2:  break;
        case M_L0:  xrow = g_inlstm + mg * IN_LSTM; break;
        case M_L1:  xrow = g_h1 + (size_t)mg * H4; break;
        default:    xrow = g_dec + (size_t)mg * DECCAT; break;
    }
    // W row (lstm: skip dead f-gate rows: logical [1024,3072) -> phys +1024)
    int gj = j0 + wrow;
    int jp = lstm ? (gj + (gj >= 1024 ? 1024 : 0)) : gj;
    const float* wp = W + (size_t)jp * K;
    bool wv_ok = gj < J;

    int warp = tid >> 5, lane = tid & 31;
    int mw = warp * 4;            // 16 warps x 4 m-rows = 64
    int j4 = lane * 4;
    u64 acc[2][4] = {};

    auto load_x = [&](int kg) -> float4 {
        float4 xv;
        if (mode == M_SP2) {
            float4 w1 = *(const float4*)(P.W_sp1 + kg);
            float4 b1 = *(const float4*)(P.b_sp1 + kg);
            xv.x = fmaxf(spd * w1.x + b1.x, 0.f);
            xv.y = fmaxf(spd * w1.y + b1.y, 0.f);
            xv.z = fmaxf(spd * w1.z + b1.z, 0.f);
            xv.w = fmaxf(spd * w1.w + b1.w, 0.f);
        } else if (mode == M_P1) {
            xv = (kg < 80) ? *(const float4*)(xrow + kg)
                           : *(const float4*)(P.spkr + mg * 64 + (kg - 80));
        } else if (mode == M_P2) {
            float4 bb = *(const float4*)(P.b_p1 + kg);
            float4 pa = __ldcg((const float4*)(g_p1_parts + (size_t)mg * 512 + kg));
            float4 pb = __ldcg((const float4*)(g_p1_parts + (size_t)(N_B + mg) * 512 + kg));
            xv.x = fmaxf(bb.x + pa.x + pb.x, 0.f);
            xv.y = fmaxf(bb.y + pa.y + pb.y, 0.f);
            xv.z = fmaxf(bb.z + pa.z + pb.z, 0.f);
            xv.w = fmaxf(bb.w + pa.w + pb.w, 0.f);
        } else if (mode == M_L0 && kg < 256) {
            float4 a4 = *(const float4*)(P.b_p2 + kg);
            #pragma unroll
            for (int s2 = 0; s2 < S_P2; s2++) {
                float4 pp = __ldcg((const float4*)(g_p2_parts + (size_t)(s2 * N_B + mg) * 256 + kg));
                a4.x += pp.x; a4.y += pp.y; a4.z += pp.z; a4.w += pp.w;
            }
            xv.x = fmaxf(a4.x, 0.f); xv.y = fmaxf(a4.y, 0.f);
            xv.z = fmaxf(a4.z, 0.f); xv.w = fmaxf(a4.w, 0.f);
        } else if (mode == M_L0 || mode == M_L1 || mode == M_OUT) {
            xv = __ldcg((const float4*)(xrow + kg));
        } else {
            xv = *(const float4*)(xrow + kg);
        }
        return xv;
    };

    float4 xv = make_float4(0, 0, 0, 0);
    if (xldr) xv = load_x(kbeg + kc);
    float4 wv = wv_ok ? *(const float4*)(wp + kbeg + kc) : make_float4(0, 0, 0, 0);

    int buf = 0;
    for (int i = 0; i < nsl; i++) {
        if (xldr) {
            Xs[buf][kc + 0][mrow] = xv.x; Xs[buf][kc + 1][mrow] = xv.y;
            Xs[buf][kc + 2][mrow] = xv.z; Xs[buf][kc + 3][mrow] = xv.w;
        }
        Ws[buf][kc + 0][wrow] = wv.x; Ws[buf][kc + 1][wrow] = wv.y;
        Ws[buf][kc + 2][wrow] = wv.z; Ws[buf][kc + 3][wrow] = wv.w;
        __syncthreads();

        if (i + 1 < nsl) {
            int kg = kbeg + (i + 1) * 16 + kc;
            if (xldr) xv = load_x(kg);
            wv = wv_ok ? *(const float4*)(wp + kg) : make_float4(0, 0, 0, 0);
        }

        #pragma unroll
        for (int kk = 0; kk < 16; kk++) {
            ulonglong2 a = *(const ulonglong2*)&Xs[buf][kk][mw];   // rows mw..mw+3
            float4 w = *(const float4*)&Ws[buf][kk][j4];
            u64 w0, w1, w2, w3;
            DUP2(w0, w.x); DUP2(w1, w.y); DUP2(w2, w.z); DUP2(w3, w.w);
            FMA2(acc[0][0], a.x, w0); FMA2(acc[0][1], a.x, w1);
            FMA2(acc[0][2], a.x, w2); FMA2(acc[0][3], a.x, w3);
            FMA2(acc[1][0], a.y, w0); FMA2(acc[1][1], a.y, w1);
            FMA2(acc[1][2], a.y, w2); FMA2(acc[1][3], a.y, w3);
        }
        buf ^= 1;
    }

    // ---- epilogue: per thread rows mw..mw+3, 4 consecutive j -> float4 ----
    int jg = j0 + j4;
    if (jg < J) {
        #pragma unroll
        for (int h = 0; h < 2; h++) {
            float4 lo4, hi4;
            UNPK(lo4.x, hi4.x, acc[h][0]);
            UNPK(lo4.y, hi4.y, acc[h][1]);
            UNPK(lo4.z, hi4.z, acc[h][2]);
            UNPK(lo4.w, hi4.w, acc[h][3]);
            int r0 = m0 + mw + 2 * h;     // lo row
            switch (mode) {
                case M_ATT: {
                    size_t base = ((size_t)s * 640 + r0) * ATT + jg;
                    *(float4*)(g_att_parts + base) = lo4;
                    *(float4*)(g_att_parts + base + ATT) = hi4;
                } break;
                case M_P1: {
                    size_t base = ((size_t)s * N_B + r0) * 512 + jg;
                    *(float4*)(g_p1_parts + base) = lo4;
                    *(float4*)(g_p1_parts + base + 512) = hi4;
                } break;
                case M_SP2: {
                    size_t base = ((size_t)s * N_B + r0) * 512 + jg;
                    *(float4*)(g_sp2_parts + base) = lo4;
                    *(float4*)(g_sp2_parts + base + 512) = hi4;
                } break;
                case M_SB: {
                    float4 a, b;
                    a.x = lo4.x / (1.f + fabsf(lo4.x)); a.y = lo4.y / (1.f + fabsf(lo4.y));
                    a.z = lo4.z / (1.f + fabsf(lo4.z)); a.w = lo4.w / (1.f + fabsf(lo4.w));
                    b.x = hi4.x / (1.f + fabsf(hi4.x)); b.y = hi4.y / (1.f + fabsf(hi4.y));
                    b.z = hi4.z / (1.f + fabsf(hi4.z)); b.w = hi4.w / (1.f + fabsf(hi4.w));
                    *(float4*)(g_sb + r0 * ATT + jg) = a;
                    *(float4*)(g_sb + (r0 + 1) * ATT + jg) = b;
                } break;
                case M_P2: {
                    size_t base = ((size_t)s * N_B + r0) * 256 + jg;
                    *(float4*)(g_p2_parts + base) = lo4;
                    *(float4*)(g_p2_parts + base + 256) = hi4;
                } break;
                case M_OUT: {
                    size_t base = ((size_t)s * N_B + r0) * OUT_J + jg;
                    *(float4*)(g_out_parts + base) = lo4;
                    *(float4*)(g_out_parts + base + OUT_J) = hi4;
                } break;
                default: {   // L0 / L1
                    size_t base = ((size_t)s * N_B + r0) * G3 + jg;
                    *(float4*)(g_lstm_parts + base) = lo4;
                    *(float4*)(g_lstm_parts + base + G3) = hi4;
                } break;
            }
        }
    }
}

// ---------------------------------------------------------------------------
// attention epilogue, 512 threads (first 256 do the ATT-dim work; all 512
// participate in __syncthreads and the ENC-dim context loop).
// ---------------------------------------------------------------------------
__device__ void att_finish_dev(int n, const Ptrs& P)
{
    __shared__ float red[80];
    __shared__ float logit_s[NWIN];
    __shared__ float att_s[NWIN];

    int a = threadIdx.x;
    int warp = a >> 5, lane = a & 31;

    float v[NWIN];
    #pragma unroll
    for (int t = 0; t < NWIN; t++) v[t] = 0.f;

    if (a < 256) {
        float sb    = __ldcg(&g_sb[n * ATT + a]);
        float spw   = P.speed[n] * P.W_speed_att[a];
        float wproj = P.W_proj[a];
        float be    = P.b_enc[a];
        #pragma unroll
        for (int t = 0; t < NWIN; t++) {
            float dot = be;
            #pragma unroll
            for (int s = 0; s < S_ATT; s++)
                dot += __ldcg(&g_att_parts[((size_t)s * 640 + n * 10 + t) * ATT + a]);
            float eb = dot / (1.f + fabsf(dot));
            float e  = eb + sb + P.conv_prev[a * 31 + (15 - t)] + spw;
            v[t] = tanhf(e) * wproj;
        }
    }
    #pragma unroll
    for (int t = 0; t < NWIN; t++) {
        #pragma unroll
        for (int o = 16; o > 0; o >>= 1)
            v[t] += __shfl_xor_sync(0xffffffffu, v[t], o);
    }
    if (lane == 0 && warp < 8) {
        #pragma unroll
        for (int t = 0; t < NWIN; t++) red[warp * NWIN + t] = v[t];
    }
    __syncthreads();
    if (a < NWIN) {
        float s = 0.f;
        #pragma unroll
        for (int w = 0; w < 8; w++) s += red[w * NWIN + a];
        logit_s[a] = s + P.b_proj[0];
    }
    __syncthreads();
    if (a == 0) {
        int len1 = max(P.lengths[n], 1) - 1;
        int hi = min(9, len1);
        float m = -1e30f;
        for (int t = 0; t <= hi; t++) m = fmaxf(m, logit_s[t]);
        float ss = 0.f;
        for (int t = 0; t < NWIN; t++) {
            float w = (t <= hi) ? expf(logit_s[t] - m) : 0.f;
            att_s[t] = w; ss += w;
        }
        float inv = 1.f / fmaxf(ss, 1e-12f);
        for (int t = 0; t < NWIN; t++) att_s[t] *= inv;
    }
    __syncthreads();

    if (a < ENC) {
        int e = a;
        float spv = P.b_sp2[e];
        #pragma unroll
        for (int s = 0; s < S_SP2; s++)
            spv += __ldcg(&g_sp2_parts[((size_t)s * N_B + n) * 512 + e]);
        float c = tanhf(spv);
        #pragma unroll
        for (int t = 0; t < NWIN; t++)
            c += att_s[t] * P.input_enc[((size_t)n * T_ENC + t) * ENC + e];
        g_inlstm[n * IN_LSTM + 256 + e] = c;
        g_dec[(size_t)n * DECCAT + H4 + e] = c;
        if (P.write_ctx) P.ctx_out[n * ENC + e] = c;
    }
    if (a < 64) g_inlstm[n * IN_LSTM + 768 + a] = P.spkr[n * 64 + a];
}

// ---------------------------------------------------------------------------
__device__ void act_dev(int layer, const Ptrs& P)
{
    const float* bih = layer ? P.bih1 : P.bih0;
    const float* bhh = layer ? P.bhh1 : P.bhh0;
    int idx = blockIdx.x * NTHR + threadIdx.x;
    if (idx < N_B * 256) {
        int n = idx >> 8, u4 = (idx & 255) * 4;
        float gi[4], gg[4], go[4];
        {
            float4 a = *(const float4*)(bih + u4);
            float4 b = *(const float4*)(bhh + u4);
            gi[0] = a.x + b.x; gi[1] = a.y + b.y; gi[2] = a.z + b.z; gi[3] = a.w + b.w;
            a = *(const float4*)(bih + 2048 + u4);
            b = *(const float4*)(bhh + 2048 + u4);
            gg[0] = a.x + b.x; gg[1] = a.y + b.y; gg[2] = a.z + b.z; gg[3] = a.w + b.w;
            a = *(const float4*)(bih + 3072 + u4);
            b = *(const float4*)(bhh + 3072 + u4);
            go[0] = a.x + b.x; go[1] = a.y + b.y; go[2] = a.z + b.z; go[3] = a.w + b.w;
        }
        #pragma unroll
        for (int s = 0; s < S_L; s++) {
            const float* p = g_lstm_parts + ((size_t)s * N_B + n) * G3;
            float4 a = __ldcg((const float4*)(p + u4));
            float4 b = __ldcg((const float4*)(p + 1024 + u4));
            float4 c = __ldcg((const float4*)(p + 2048 + u4));
            gi[0] += a.x; gi[1] += a.y; gi[2] += a.z; gi[3] += a.w;
            gg[0] += b.x; gg[1] += b.y; gg[2] += b.z; gg[3] += b.w;
            go[0] += c.x; go[1] += c.y; go[2] += c.z; go[3] += c.w;
        }
        float4 h;
        float* hp = &h.x;
        #pragma unroll
        for (int q = 0; q < 4; q++) {
            float c = sigm(gi[q]) * tanhf(gg[q]);
            hp[q] = sigm(go[q]) * tanhf(c);
        }
        if (layer == 0) *(float4*)(g_h1 + n * H4 + u4) = h;
        else            *(float4*)(g_dec + (size_t)n * DECCAT + u4) = h;
    }
}

// ---------------------------------------------------------------------------
__global__ void __launch_bounds__(NTHR, 1) fused_k(Ptrs P)
{
    __shared__ __align__(16) float Xs[2][16][68];
    __shared__ __align__(16) float Ws[2][16][132];

    unsigned s0 = 0;
    if (threadIdx.x == 0) s0 = g_sense;
    int b = blockIdx.x;

    // ---- stage A: ATT(120) + P1(8) + SP2(16) + SB(2) = 146 tasks ----
    if (b < 146) {
        int mode, jt, s = 0, mt = 0;
        if (b < 120)      { mode = M_ATT; jt = b & 1; int r = b >> 1; s = r % 6; mt = r / 6; }
        else if (b < 128) { int t = b - 120; mode = M_P1;  jt = t & 3; s = t >> 2; }
        else if (b < 144) { int t = b - 128; mode = M_SP2; jt = t & 3; s = t >> 2; }
        else              { mode = M_SB;  jt = b - 144; }
        gemm_tile(mode, jt, s, mt, P, Xs, Ws);
    }
    gbar(s0 + 1);

    // ---- stage B: att_finish(64) + P2 GEMM(16) ----
    if (b < 64) att_finish_dev(b, P);
    else if (b < 80) { int t = b - 64; gemm_tile(M_P2, t & 1, t >> 1, 0, P, Xs, Ws); }
    gbar(s0 + 2);

    // ---- stage C: LSTM0 GEMM (24 jt x 6 s = 144); prenet2 act in loader ----
    if (b < 144) gemm_tile(M_L0, b % 24, b / 24, 0, P, Xs, Ws);
    gbar(s0 + 3);

    // ---- stage D: LSTM0 activation ----
    act_dev(0, P);
    gbar(s0 + 4);

    // ---- stage E: LSTM1 GEMM ----
    if (b < 144) gemm_tile(M_L1, b % 24, b / 24, 0, P, Xs, Ws);
    gbar(s0 + 5);

    // ---- stage F: LSTM1 activation ----
    act_dev(1, P);
    gbar(s0 + 6);

    // ---- stage G: output GEMM (2 jt x 32 s = 64) ----
    if (b < 64) gemm_tile(M_OUT, b & 1, b >> 1, 0, P, Xs, Ws);
    gbar(s0 + 7);

    // ---- stage H: output reduction ----
    int gt = b * NTHR + threadIdx.x;
    if (gt < N_B * OUT_J) {
        int n = gt / OUT_J, j = gt - n * OUT_J;
        float a = P.b_out[j];
        #pragma unroll
        for (int s = 0; s < S_OUT; s++)
            a += __ldcg(&g_out_parts[((size_t)s * N_B + n) * OUT_J + j]);
        P.out[n * OUT_J + j] = a;
    }
}

// ---------------------------------------------------------------------------
extern "C" void kernel_launch(void* const* d_in, const int* in_sizes, int n_in,
                              void* d_out, int out_size)
{
    Ptrs P;
    P.input_enc   = (const float*)d_in[0];
    P.input_dec   = (const float*)d_in[1];
    P.spkr        = (const float*)d_in[2];
    P.lengths     = (const int*)  d_in[3];
    P.speed       = (const float*)d_in[4];
    P.W_enc       = (const float*)d_in[5];
    P.b_enc       = (const float*)d_in[6];
    P.W_spkr      = (const float*)d_in[7];
    P.conv_prev   = (const float*)d_in[8];
    P.W_speed_att = (const float*)d_in[9];
    P.W_proj      = (const float*)d_in[10];
    P.b_proj      = (const float*)d_in[11];
    P.W_sp1       = (const float*)d_in[12];
    P.b_sp1       = (const float*)d_in[13];
    P.W_sp2       = (const float*)d_in[14];
    P.b_sp2       = (const float*)d_in[15];
    P.W_p1        = (const float*)d_in[16];
    P.b_p1        = (const float*)d_in[17];
    P.W_p2        = (const float*)d_in[18];
    P.b_p2        = (const float*)d_in[19];
    P.Wih0        = (const float*)d_in[20];
    P.bih0        = (const float*)d_in[22];
    P.bhh0        = (const float*)d_in[23];
    P.Wih1        = (const float*)d_in[24];
    P.bih1        = (const float*)d_in[26];
    P.bhh1        = (const float*)d_in[27];
    P.W_out       = (const float*)d_in[28];
    P.b_out       = (const float*)d_in[29];

    float* out = (float*)d_out;
    P.out = out;
    P.write_ctx = (out_size >= N_B * 2 * 80 + N_B * ENC) ? 1 : 0;
    P.ctx_out = out + N_B * 2 * 80;

    fused_k<<<GRID, NTHR>>>(P);
}